// round 2
// baseline (speedup 1.0000x reference)
#include <cuda_runtime.h>

// Butterfly (untied, increasing stride) for n=1024, 10 stages, batch 32768.
// out[b] = B(x[b]) + bias.
//
// Radix-4 register-resident design: 5 phases x 2 stages. Each thread owns a
// float4 "quad" of 4 elements with stride S=4^q inside a group of 4S, for
// 8 rows at a time. Between phases, data is remapped through swizzled smem.
// Twiddles (80KB) are staged into smem once per block in a permuted layout so
// each phase reads exactly plane[t] and plane[t+256] (conflict-free).
// Remaps for q=0,1 are intra-warp (exchange groups of 4/16 lanes; swizzle
// only perturbs bits [0:3) of the granule index) -> __syncwarp suffices.

#define NFLOAT 1024
#define NG     256          // float4 granules per row
#define BLOCK  256
#define RPT    8            // rows per tile
#define NROWS  32768
#define NTILES (NROWS / RPT)   // 4096
#define TW_F4  5120         // 10 planes * 512 pairs (float4 each)
#define GRID   296

__device__ __forceinline__ int swz(int g) { return g ^ ((g >> 2) & 7); }

__device__ __forceinline__ void bfly(float& a, float& b, const float4 t) {
    // new_a = t00*a + t01*b ; new_b = t10*a + t11*b
    float na = fmaf(t.y, b, t.x * a);
    float nb = fmaf(t.w, b, t.z * a);
    a = na; b = nb;
}

__global__ __launch_bounds__(BLOCK, 2)
void butterfly_kernel(const float4* __restrict__ x4,
                      const float4* __restrict__ tw4,
                      const float*  __restrict__ bias,
                      float*        __restrict__ out)
{
    extern __shared__ float4 sm4[];
    float4* tw_s = sm4;            // 5120 float4 = 80KB
    float4* buf  = sm4 + TW_F4;    // 2048 float4 = 32KB (8 rows x 256 granules)

    const int t = threadIdx.x;

    // ---- Stage twiddles into smem, permuted so that for phase q (S=4^q,
    // thread t = c*S + d) the two needed pairs pA=2cS+d and pB=pA+S live at
    // plane[t] and plane[t+256]. ----
    for (int i = t; i < TW_F4; i += BLOCK) {
        int ls = i >> 9;          // log_stride plane 0..9
        int p  = i & 511;         // pair index within plane
        int q  = ls >> 1;         // phase
        int lq = 2 * q;           // log2(S)
        int S  = 1 << lq;
        int g  = p >> (lq + 1);   // p / (2S)
        int h  = (p >> lq) & 1;   // A/B half
        int d  = p & (S - 1);
        int phys = (ls << 9) + g * S + d + (h << 8);
        tw_s[phys] = tw4[i];
    }
    __syncthreads();

    // Bias for the final-phase ownership: thread t owns elements k*256 + t.
    const float b0 = bias[t];
    const float b1 = bias[256 + t];
    const float b2 = bias[512 + t];
    const float b3 = bias[768 + t];

    for (int tile = blockIdx.x; tile < NTILES; tile += gridDim.x) {
        const int row0 = tile * RPT;

        float4 v[RPT];
        // Phase-0 layout: thread t owns contiguous quad [4t, 4t+4) -> coalesced float4 load.
        #pragma unroll
        for (int r = 0; r < RPT; r++)
            v[r] = x4[(size_t)(row0 + r) * NG + t];

        #pragma unroll
        for (int q = 0; q < 5; q++) {
            const int lq = 2 * q;
            const int S  = 1 << lq;

            // Twiddles for strides S (plane 2q) and 2S (plane 2q+1).
            const float4 TA0 = tw_s[(2 * q)     * 512 + t];
            const float4 TB0 = tw_s[(2 * q)     * 512 + 256 + t];
            const float4 TA1 = tw_s[(2 * q + 1) * 512 + t];
            const float4 TB1 = tw_s[(2 * q + 1) * 512 + 256 + t];

            #pragma unroll
            for (int r = 0; r < RPT; r++) {
                // stride S: (k0,k1) and (k2,k3)
                bfly(v[r].x, v[r].y, TA0);
                bfly(v[r].z, v[r].w, TB0);
                // stride 2S: (k0,k2) and (k1,k3)
                bfly(v[r].x, v[r].z, TA1);
                bfly(v[r].y, v[r].w, TB1);
            }

            if (q < 4) {
                // Remap to next phase (S' = 4S). Current thread t = c*S + d.
                // Element k goes to next-phase thread t' = (c/4)*4S + k*S + d,
                // quad slot k' = c&3. Stored at float4 granule swz(t'), byte-lane k'.
                const int c    = t >> lq;
                const int d    = t & (S - 1);
                const int base = ((c >> 2) << (lq + 2)) + d;  // (c/4)*4S + d
                const int off  = c & 3;

                // q=0: exchange within lane-groups of 4; q=1: within 16.
                // Both stay inside one warp's 32-granule region (swz keeps the
                // aligned 8-block), so warp-level sync is sufficient and there
                // is no cross-warp WAR on buf for these phases.
                if (q < 2) __syncwarp();
                else       __syncthreads();   // prior reads complete before overwrite
                #pragma unroll
                for (int r = 0; r < RPT; r++) {
                    float* bro = (float*)(buf + r * NG);
                    bro[swz(base        ) * 4 + off] = v[r].x;
                    bro[swz(base +     S) * 4 + off] = v[r].y;
                    bro[swz(base + 2 * S) * 4 + off] = v[r].z;
                    bro[swz(base + 3 * S) * 4 + off] = v[r].w;
                }
                if (q < 2) __syncwarp();
                else       __syncthreads();
                const int rg = swz(t);
                #pragma unroll
                for (int r = 0; r < RPT; r++)
                    v[r] = buf[r * NG + rg];
            }
        }

        // Final ownership: thread t holds elements {t, 256+t, 512+t, 768+t}.
        // Scalar stores are fully coalesced (128B per warp per k).
        #pragma unroll
        for (int r = 0; r < RPT; r++) {
            float* o = out + (size_t)(row0 + r) * NFLOAT;
            o[t]       = v[r].x + b0;
            o[256 + t] = v[r].y + b1;
            o[512 + t] = v[r].z + b2;
            o[768 + t] = v[r].w + b3;
        }
    }
}

extern "C" void kernel_launch(void* const* d_in, const int* in_sizes, int n_in,
                              void* d_out, int out_size)
{
    // Identify inputs by element count (x=33554432, twiddle=20480, bias=1024),
    // falling back to positional order (x, twiddle, bias).
    const float* px  = (n_in > 0) ? (const float*)d_in[0] : nullptr;
    const float* ptw = (n_in > 1) ? (const float*)d_in[1] : nullptr;
    const float* pb  = (n_in > 2) ? (const float*)d_in[2] : nullptr;
    for (int i = 0; i < n_in; i++) {
        if (in_sizes[i] == 33554432)      px  = (const float*)d_in[i];
        else if (in_sizes[i] == 20480)    ptw = (const float*)d_in[i];
        else if (in_sizes[i] == 1024)     pb  = (const float*)d_in[i];
    }

    const int smem_bytes = (TW_F4 + RPT * NG) * 16;   // 114688 B
    cudaFuncSetAttribute(butterfly_kernel,
                         cudaFuncAttributeMaxDynamicSharedMemorySize,
                         smem_bytes);

    butterfly_kernel<<<GRID, BLOCK, smem_bytes>>>(
        (const float4*)px, (const float4*)ptw, pb, (float*)d_out);
}

// round 4
// speedup vs baseline: 1.3161x; 1.3161x over previous
#include <cuda_runtime.h>

// Butterfly (untied, increasing stride), n=1024, 10 stages, batch 32768.
// out[b] = B(x[b]) + bias.
//
// Radix-4: 5 phases x 2 stages. Thread t owns 4 elements {c*4S + k*S + d},
// S=4^q, c=t>>2q, d=t&(S-1), for 8 rows at a time.
//  - Twiddles for phases 0-3 are hoisted into registers (loop-invariant).
//  - Boundaries q0->q1 and q1->q2 are intra-lane-group 4x4 transposes done
//    with warp shuffles (no smem).
//  - Boundaries q2->q3 and q3->q4 go through double-buffered swizzled smem
//    (buffer A / buffer B), needing only ONE __syncthreads each.
//  - Phase-4 twiddles (planes 8,9; permutation = identity at S=256) live in
//    a 16KB smem array, 4 LDS.128 per tile reused across 8 rows.

#define NFLOAT 1024
#define NG     256
#define BLOCK  256
#define RPT    8
#define NROWS  32768
#define NTILES (NROWS / RPT)   // 4096
#define GRID   296

__device__ __forceinline__ int swz(int g) { return g ^ ((g >> 2) & 7); }

__device__ __forceinline__ void bfly(float& a, float& b, const float4 t) {
    float na = fmaf(t.y, b, t.x * a);
    float nb = fmaf(t.w, b, t.z * a);
    a = na; b = nb;
}

// 4x4 transpose of v.{x,y,z,w} across a lane group, xor strides m0 and m1=2*m0.
// b0 = (lane>>log2(m0))&1, b1 = (lane>>log2(m1))&1.
__device__ __forceinline__ void lane_transpose(float4& v, int b0, int b1,
                                               int m0, int m1) {
    // round 1: swap slot-bit0 with lane-bit(log2 m0)
    float s0 = b0 ? v.x : v.y;
    float s1 = b0 ? v.z : v.w;
    float r0 = __shfl_xor_sync(0xFFFFFFFFu, s0, m0);
    float r1 = __shfl_xor_sync(0xFFFFFFFFu, s1, m0);
    if (b0) { v.x = r0; v.z = r1; } else { v.y = r0; v.w = r1; }
    // round 2: swap slot-bit1 with lane-bit(log2 m1)
    s0 = b1 ? v.x : v.z;
    s1 = b1 ? v.y : v.w;
    r0 = __shfl_xor_sync(0xFFFFFFFFu, s0, m1);
    r1 = __shfl_xor_sync(0xFFFFFFFFu, s1, m1);
    if (b1) { v.x = r0; v.y = r1; } else { v.z = r0; v.w = r1; }
}

__global__ __launch_bounds__(BLOCK, 2)
void butterfly_kernel(const float4* __restrict__ x4,
                      const float4* __restrict__ tw4,
                      const float*  __restrict__ bias,
                      float*        __restrict__ out)
{
    extern __shared__ float4 sm4[];
    float4* tws  = sm4;            // planes 8,9: 1024 float4 = 16KB
    float4* bufA = sm4 + 1024;     // 2048 float4 = 32KB
    float4* bufB = sm4 + 3072;     // 2048 float4 = 32KB

    const int t = threadIdx.x;

    // Stage planes 8,9 (identity permutation at S=256).
    for (int i = t; i < 1024; i += BLOCK)
        tws[i] = tw4[4096 + i];
    __syncthreads();

    // Hoist twiddles for phases 0..3 into registers.
    // Phase q: TA0 = P[2q][2cS+d], TB0 = P[2q][2cS+S+d],
    //          TA1 = P[2q+1][2cS+d], TB1 = P[2q+1][2cS+S+d].
    float4 TA0r[4], TB0r[4], TA1r[4], TB1r[4];
    #pragma unroll
    for (int q = 0; q < 4; q++) {
        const int lq = 2 * q;
        const int S  = 1 << lq;
        const int c  = t >> lq;
        const int d  = t & (S - 1);
        const int pA = 2 * c * S + d;
        TA0r[q] = tw4[(2 * q)     * 512 + pA];
        TB0r[q] = tw4[(2 * q)     * 512 + pA + S];
        TA1r[q] = tw4[(2 * q + 1) * 512 + pA];
        TB1r[q] = tw4[(2 * q + 1) * 512 + pA + S];
    }

    const float b0 = bias[t];
    const float b1 = bias[256 + t];
    const float b2 = bias[512 + t];
    const float b3 = bias[768 + t];

    const int l0 = t & 1, l1 = (t >> 1) & 1;        // q0 transpose bits
    const int l2 = (t >> 2) & 1, l3 = (t >> 3) & 1; // q1 transpose bits

    for (int tile = blockIdx.x; tile < NTILES; tile += gridDim.x) {
        const int row0 = tile * RPT;

        float4 v[RPT];
        #pragma unroll
        for (int r = 0; r < RPT; r++)
            v[r] = x4[(size_t)(row0 + r) * NG + t];

        // ---- phase 0 (S=1) + shuffle boundary (4-lane groups) ----
        #pragma unroll
        for (int r = 0; r < RPT; r++) {
            bfly(v[r].x, v[r].y, TA0r[0]);
            bfly(v[r].z, v[r].w, TB0r[0]);
            bfly(v[r].x, v[r].z, TA1r[0]);
            bfly(v[r].y, v[r].w, TB1r[0]);
            lane_transpose(v[r], l0, l1, 1, 2);
        }

        // ---- phase 1 (S=4) + shuffle boundary (16-lane groups) ----
        #pragma unroll
        for (int r = 0; r < RPT; r++) {
            bfly(v[r].x, v[r].y, TA0r[1]);
            bfly(v[r].z, v[r].w, TB0r[1]);
            bfly(v[r].x, v[r].z, TA1r[1]);
            bfly(v[r].y, v[r].w, TB1r[1]);
            lane_transpose(v[r], l2, l3, 4, 8);
        }

        // ---- phase 2 (S=16) + smem boundary via bufA ----
        #pragma unroll
        for (int r = 0; r < RPT; r++) {
            bfly(v[r].x, v[r].y, TA0r[2]);
            bfly(v[r].z, v[r].w, TB0r[2]);
            bfly(v[r].x, v[r].z, TA1r[2]);
            bfly(v[r].y, v[r].w, TB1r[2]);
        }
        {
            const int lq = 4, S = 16;
            const int c = t >> lq, d = t & (S - 1);
            const int base = ((c >> 2) << (lq + 2)) + d;
            const int off  = c & 3;
            #pragma unroll
            for (int r = 0; r < RPT; r++) {
                float* bro = (float*)(bufA + r * NG);
                bro[swz(base        ) * 4 + off] = v[r].x;
                bro[swz(base +     S) * 4 + off] = v[r].y;
                bro[swz(base + 2 * S) * 4 + off] = v[r].z;
                bro[swz(base + 3 * S) * 4 + off] = v[r].w;
            }
            __syncthreads();
            const int rg = swz(t);
            #pragma unroll
            for (int r = 0; r < RPT; r++)
                v[r] = bufA[r * NG + rg];
        }

        // ---- phase 3 (S=64) + smem boundary via bufB ----
        #pragma unroll
        for (int r = 0; r < RPT; r++) {
            bfly(v[r].x, v[r].y, TA0r[3]);
            bfly(v[r].z, v[r].w, TB0r[3]);
            bfly(v[r].x, v[r].z, TA1r[3]);
            bfly(v[r].y, v[r].w, TB1r[3]);
        }
        {
            const int lq = 6, S = 64;
            const int c = t >> lq, d = t & (S - 1);
            const int base = ((c >> 2) << (lq + 2)) + d;
            const int off  = c & 3;
            #pragma unroll
            for (int r = 0; r < RPT; r++) {
                float* bro = (float*)(bufB + r * NG);
                bro[swz(base        ) * 4 + off] = v[r].x;
                bro[swz(base +     S) * 4 + off] = v[r].y;
                bro[swz(base + 2 * S) * 4 + off] = v[r].z;
                bro[swz(base + 3 * S) * 4 + off] = v[r].w;
            }
            __syncthreads();
            const int rg = swz(t);
            #pragma unroll
            for (int r = 0; r < RPT; r++)
                v[r] = bufB[r * NG + rg];
        }

        // ---- phase 4 (S=256): twiddles from smem, then bias + store ----
        {
            const float4 TA0 = tws[t];
            const float4 TB0 = tws[256 + t];
            const float4 TA1 = tws[512 + t];
            const float4 TB1 = tws[768 + t];
            #pragma unroll
            for (int r = 0; r < RPT; r++) {
                bfly(v[r].x, v[r].y, TA0);
                bfly(v[r].z, v[r].w, TB0);
                bfly(v[r].x, v[r].z, TA1);
                bfly(v[r].y, v[r].w, TB1);
                float* o = out + (size_t)(row0 + r) * NFLOAT;
                o[t]       = v[r].x + b0;
                o[256 + t] = v[r].y + b1;
                o[512 + t] = v[r].z + b2;
                o[768 + t] = v[r].w + b3;
            }
        }
    }
}

extern "C" void kernel_launch(void* const* d_in, const int* in_sizes, int n_in,
                              void* d_out, int out_size)
{
    const float* px  = (n_in > 0) ? (const float*)d_in[0] : nullptr;
    const float* ptw = (n_in > 1) ? (const float*)d_in[1] : nullptr;
    const float* pb  = (n_in > 2) ? (const float*)d_in[2] : nullptr;
    for (int i = 0; i < n_in; i++) {
        if (in_sizes[i] == 33554432)      px  = (const float*)d_in[i];
        else if (in_sizes[i] == 20480)    ptw = (const float*)d_in[i];
        else if (in_sizes[i] == 1024)     pb  = (const float*)d_in[i];
    }

    const int smem_bytes = (1024 + 2048 + 2048) * 16;   // 81920 B
    cudaFuncSetAttribute(butterfly_kernel,
                         cudaFuncAttributeMaxDynamicSharedMemorySize,
                         smem_bytes);

    butterfly_kernel<<<GRID, BLOCK, smem_bytes>>>(
        (const float4*)px, (const float4*)ptw, pb, (float*)d_out);
}

// round 6
// speedup vs baseline: 1.3846x; 1.0521x over previous
#include <cuda_runtime.h>

// Butterfly (untied, increasing stride), n=1024, 10 stages, batch 32768.
// out[b] = B(x[b]) + bias.
//
// Radix-4: 5 phases x 2 stages. Thread t at phase q (S=4^q, c=t>>2q,
// d=t&(S-1)) owns elements {c*4S + k*S + d}, slot k, for 8 rows.
// Each phase boundary = transpose of slot bits (k1,k0) with thread bits
// (lq+1, lq), decomposed into two 1-bit swaps:
//   k0 <-> t_b : thread exchanges (x,z)/(y,w) halves with partner t^2^b
//   k1 <-> t_b : thread exchanges (x,y)/(z,w) halves with partner t^2^b
// Lane-bit swaps (b<=4) use shuffles; higher bits use conflict-free
// float2 smem passes (STS.64/LDS.64, own-slot store, partner-slot load).
//   q0: shfl(1), shfl(2);  q1: shfl(4), shfl(8)
//   q2: shfl(16), smem(32);  q3: smem(64), smem(128)
// Twiddles: phases 0,1 register-resident; phases 2,3,4 staged per-thread
// into smem (4 conflict-free LDS.128 per phase per tile, reused x8 rows).

#define NFLOAT 1024
#define BLOCK  256
#define RPT    8
#define NROWS  32768
#define NTILES (NROWS / RPT)   // 4096
#define GRID   296

__device__ __forceinline__ void bfly(float& a, float& b, const float4 t) {
    float na = fmaf(t.y, b, t.x * a);
    float nb = fmaf(t.w, b, t.z * a);
    a = na; b = nb;
}

// slot-bit0 <-> lane-bit swap: exchanges (x,z)/(y,w) with lane^m.
__device__ __forceinline__ void swap_k0_shfl(float4& v, int b0, int m) {
    float s0 = b0 ? v.x : v.y;
    float s1 = b0 ? v.z : v.w;
    float r0 = __shfl_xor_sync(0xFFFFFFFFu, s0, m);
    float r1 = __shfl_xor_sync(0xFFFFFFFFu, s1, m);
    if (b0) { v.x = r0; v.z = r1; } else { v.y = r0; v.w = r1; }
}
// slot-bit1 <-> lane-bit swap: exchanges (x,y)/(z,w) with lane^m.
__device__ __forceinline__ void swap_k1_shfl(float4& v, int b1, int m) {
    float s0 = b1 ? v.x : v.z;
    float s1 = b1 ? v.y : v.w;
    float r0 = __shfl_xor_sync(0xFFFFFFFFu, s0, m);
    float r1 = __shfl_xor_sync(0xFFFFFFFFu, s1, m);
    if (b1) { v.x = r0; v.y = r1; } else { v.z = r0; v.w = r1; }
}

__global__ __launch_bounds__(BLOCK, 2)
void butterfly_kernel(const float4* __restrict__ x4,
                      const float4* __restrict__ tw4,
                      const float*  __restrict__ bias,
                      float*        __restrict__ out)
{
    extern __shared__ float4 sm4[];
    float4* tw2  = sm4;           // 1024 f4 = 16KB (phase-2 twiddles)
    float4* tw3  = sm4 + 1024;    // 16KB (phase-3)
    float4* tw4s = sm4 + 2048;    // 16KB (phase-4)
    float2* P0 = (float2*)(sm4 + 3072);   // 2048 f2 = 16KB (pass t^32)
    float2* P1 = P0 + 2048;               // 16KB (pass t^64)
    float2* P2 = P1 + 2048;               // 16KB (pass t^128)

    const int t = threadIdx.x;

    // ---- Stage per-thread twiddles for phases 2,3,4 into smem ----
    {
        // q=2: S=16
        int c = t >> 4, d = t & 15, pA = (c << 5) + d;
        tw2[t]       = tw4[2048 + pA];
        tw2[256 + t] = tw4[2048 + pA + 16];
        tw2[512 + t] = tw4[2560 + pA];
        tw2[768 + t] = tw4[2560 + pA + 16];
        // q=3: S=64
        c = t >> 6; d = t & 63; pA = (c << 7) + d;
        tw3[t]       = tw4[3072 + pA];
        tw3[256 + t] = tw4[3072 + pA + 64];
        tw3[512 + t] = tw4[3584 + pA];
        tw3[768 + t] = tw4[3584 + pA + 64];
        // q=4: S=256, pA = t
        tw4s[t]       = tw4[4096 + t];
        tw4s[256 + t] = tw4[4352 + t];
        tw4s[512 + t] = tw4[4608 + t];
        tw4s[768 + t] = tw4[4864 + t];
    }

    // ---- Register twiddles for phases 0,1 ----
    float4 TA00, TB00, TA10, TB10, TA01, TB01, TA11, TB11;
    {
        int pA = 2 * t;                       // q=0
        TA00 = tw4[pA];        TB00 = tw4[pA + 1];
        TA10 = tw4[512 + pA];  TB10 = tw4[512 + pA + 1];
        int c = t >> 2, d = t & 3; pA = (c << 3) + d;   // q=1
        TA01 = tw4[1024 + pA]; TB01 = tw4[1024 + pA + 4];
        TA11 = tw4[1536 + pA]; TB11 = tw4[1536 + pA + 4];
    }

    const float b0 = bias[t];
    const float b1 = bias[256 + t];
    const float b2 = bias[512 + t];
    const float b3 = bias[768 + t];

    const int l0 = t & 1,        l1 = (t >> 1) & 1;
    const int l2 = (t >> 2) & 1, l3 = (t >> 3) & 1;
    const int l4 = (t >> 4) & 1;
    const int e5 = t & 32, e6 = t & 64, e7 = t & 128;

    __syncthreads();   // twiddle staging visible

    for (int tile = blockIdx.x; tile < NTILES; tile += gridDim.x) {
        const int row0 = tile * RPT;

        float4 v[RPT];
        #pragma unroll
        for (int r = 0; r < RPT; r++)
            v[r] = x4[(size_t)(row0 + r) * 256 + t];

        // ---- phase 0 (S=1): reg twiddles + shuffle swaps (bits 0,1) ----
        #pragma unroll
        for (int r = 0; r < RPT; r++) {
            bfly(v[r].x, v[r].y, TA00);
            bfly(v[r].z, v[r].w, TB00);
            bfly(v[r].x, v[r].z, TA10);
            bfly(v[r].y, v[r].w, TB10);
            swap_k0_shfl(v[r], l0, 1);
            swap_k1_shfl(v[r], l1, 2);
        }

        // ---- phase 1 (S=4): reg twiddles + shuffle swaps (bits 2,3) ----
        #pragma unroll
        for (int r = 0; r < RPT; r++) {
            bfly(v[r].x, v[r].y, TA01);
            bfly(v[r].z, v[r].w, TB01);
            bfly(v[r].x, v[r].z, TA11);
            bfly(v[r].y, v[r].w, TB11);
            swap_k0_shfl(v[r], l2, 4);
            swap_k1_shfl(v[r], l3, 8);
        }

        // ---- phase 2 (S=16): smem twiddles; shfl(bit4) + smem pass(bit5) ----
        {
            const float4 A0 = tw2[t],       B0 = tw2[256 + t];
            const float4 A1 = tw2[512 + t], B1 = tw2[768 + t];
            #pragma unroll
            for (int r = 0; r < RPT; r++) {
                bfly(v[r].x, v[r].y, A0);
                bfly(v[r].z, v[r].w, B0);
                bfly(v[r].x, v[r].z, A1);
                bfly(v[r].y, v[r].w, B1);
                swap_k0_shfl(v[r], l4, 16);
                // k1 <-> t5: store outgoing half
                P0[r * 256 + t] = e5 ? make_float2(v[r].x, v[r].y)
                                     : make_float2(v[r].z, v[r].w);
            }
            __syncthreads();
            #pragma unroll
            for (int r = 0; r < RPT; r++) {
                float2 in = P0[r * 256 + (t ^ 32)];
                if (e5) { v[r].x = in.x; v[r].y = in.y; }
                else    { v[r].z = in.x; v[r].w = in.y; }
            }
        }

        // ---- phase 3 (S=64): smem twiddles; smem passes (bits 6,7) ----
        {
            const float4 A0 = tw3[t],       B0 = tw3[256 + t];
            const float4 A1 = tw3[512 + t], B1 = tw3[768 + t];
            #pragma unroll
            for (int r = 0; r < RPT; r++) {
                bfly(v[r].x, v[r].y, A0);
                bfly(v[r].z, v[r].w, B0);
                bfly(v[r].x, v[r].z, A1);
                bfly(v[r].y, v[r].w, B1);
                // k0 <-> t6
                P1[r * 256 + t] = e6 ? make_float2(v[r].x, v[r].z)
                                     : make_float2(v[r].y, v[r].w);
            }
            __syncthreads();
            #pragma unroll
            for (int r = 0; r < RPT; r++) {
                float2 in = P1[r * 256 + (t ^ 64)];
                if (e6) { v[r].x = in.x; v[r].z = in.y; }
                else    { v[r].y = in.x; v[r].w = in.y; }
                // k1 <-> t7
                P2[r * 256 + t] = e7 ? make_float2(v[r].x, v[r].y)
                                     : make_float2(v[r].z, v[r].w);
            }
            __syncthreads();
            #pragma unroll
            for (int r = 0; r < RPT; r++) {
                float2 in = P2[r * 256 + (t ^ 128)];
                if (e7) { v[r].x = in.x; v[r].y = in.y; }
                else    { v[r].z = in.x; v[r].w = in.y; }
            }
        }

        // ---- phase 4 (S=256): smem twiddles, bias, store ----
        {
            const float4 A0 = tw4s[t],       B0 = tw4s[256 + t];
            const float4 A1 = tw4s[512 + t], B1 = tw4s[768 + t];
            #pragma unroll
            for (int r = 0; r < RPT; r++) {
                bfly(v[r].x, v[r].y, A0);
                bfly(v[r].z, v[r].w, B0);
                bfly(v[r].x, v[r].z, A1);
                bfly(v[r].y, v[r].w, B1);
                float* o = out + (size_t)(row0 + r) * NFLOAT;
                o[t]       = v[r].x + b0;
                o[256 + t] = v[r].y + b1;
                o[512 + t] = v[r].z + b2;
                o[768 + t] = v[r].w + b3;
            }
        }
    }
}

extern "C" void kernel_launch(void* const* d_in, const int* in_sizes, int n_in,
                              void* d_out, int out_size)
{
    const float* px  = (n_in > 0) ? (const float*)d_in[0] : nullptr;
    const float* ptw = (n_in > 1) ? (const float*)d_in[1] : nullptr;
    const float* pb  = (n_in > 2) ? (const float*)d_in[2] : nullptr;
    for (int i = 0; i < n_in; i++) {
        if (in_sizes[i] == 33554432)      px  = (const float*)d_in[i];
        else if (in_sizes[i] == 20480)    ptw = (const float*)d_in[i];
        else if (in_sizes[i] == 1024)     pb  = (const float*)d_in[i];
    }

    const int smem_bytes = 3072 * 16 + 3 * 2048 * 8;   // 48KB tw + 48KB bufs = 98304
    cudaFuncSetAttribute(butterfly_kernel,
                         cudaFuncAttributeMaxDynamicSharedMemorySize,
                         smem_bytes);

    butterfly_kernel<<<GRID, BLOCK, smem_bytes>>>(
        (const float4*)px, (const float4*)ptw, pb, (float*)d_out);
}